// round 4
// baseline (speedup 1.0000x reference)
#include <cuda_runtime.h>
#include <cstddef>
#include <cstdint>

// HardDTW max-plus scan — 4-CTA cluster K-split, 8-level skewed wavefront.
//
//   out[b,0,k] = x[b,0,k]
//   out[b,t,k] = x[b,t,k] + max(out[b,t-1,k], out[b,t-1,k-1])   (k-1 < 0 -> -inf)
//
// Grid = B*4 CTAs; cluster of 4 CTAs covers one batch, rank r owns columns
// [r*256, r*256+256). 64 threads/CTA (2 warps), thread carries one float4.
// Pipeline levels = rank*2 + warp (8 levels), each skewed CHUNK=16 steps.
// Warp0->warp1 edges via local smem; CTA r warp1 -> CTA r+1 warp0 edges via
// DSMEM (st.shared::cluster through mapa). One cluster.sync per epoch provides
// the barrier + cluster-scope release/acquire for all edge traffic.

namespace {
constexpr int T = 2048;
constexpr int K = 1024;
constexpr int NSPLIT = 4;
constexpr int KSUB = K / NSPLIT;            // 256
constexpr int THREADS = KSUB / 4;           // 64
constexpr int NWARP = THREADS / 32;         // 2
constexpr int LEVELS = NSPLIT * NWARP;      // 8
constexpr int RS = K / 4;                   // float4 per full row = 256
constexpr int CHUNK = 16;
constexpr int NCHUNK = T / CHUNK;           // 128
constexpr int NEPOCH = NCHUNK + LEVELS - 1; // 135
}

__global__ __launch_bounds__(THREADS, 1) __cluster_dims__(NSPLIT, 1, 1)
void harddtw_cluster_kernel(const float* __restrict__ x, float* __restrict__ out) {
    __shared__ float wedges[2][CHUNK];   // warp0 -> warp1 (local smem)
    __shared__ float cedges[2][CHUNK];   // prev CTA's warp1 -> our warp0 (remote-written)

    const int tid   = threadIdx.x;
    const int lane  = tid & 31;
    const int warp  = tid >> 5;
    const int rank  = blockIdx.x & (NSPLIT - 1);
    const int batch = blockIdx.x >> 2;
    const int level = rank * NWARP + warp;
    const float NEG_INF = __int_as_float(0xff800000);

    const float4* __restrict__ xr =
        reinterpret_cast<const float4*>(x + (size_t)batch * T * K)
        + rank * (KSUB / 4) + tid;
    float4* __restrict__ orow =
        reinterpret_cast<float4*>(out + (size_t)batch * T * K)
        + rank * (KSUB / 4) + tid;

    // DSMEM address of cedges in the next-rank CTA.
    uint32_t ced_local = (uint32_t)__cvta_generic_to_shared(&cedges[0][0]);
    uint32_t ced_remote;
    {
        int tgt = (rank + 1 < NSPLIT) ? (rank + 1) : rank;  // harmless self-map for rank 3
        asm("mapa.shared::cluster.u32 %0, %1, %2;"
            : "=r"(ced_remote) : "r"(ced_local), "r"(tgt));
    }

    const bool wprod = (warp == 0) && (lane == 31);  // feeds warp 1 (local)
    const bool cprod = (warp == NWARP - 1) && (lane == 31) && (rank < NSPLIT - 1);
    const int bl = (lane < CHUNK) ? lane : (CHUNK - 1);

    // Rolling x prefetch queue: chunk c+1 loaded while processing chunk c.
    float4 xq[CHUNK];
#pragma unroll
    for (int j = 0; j < CHUNK; ++j) xq[j] = xr[(size_t)j * RS];

    float4 cur = make_float4(NEG_INF, NEG_INF, NEG_INF, NEG_INF);

    for (int e = 0; e < NEPOCH; ++e) {
        const int c = e - level;
        if (0 <= c && c < NCHUNK) {
            const int t0 = c * CHUNK;

            // Upstream boundary vector (written during epoch e-1).
            const int rbuf = (e - 1) & 1;
            float bv = (warp == 0) ? cedges[rbuf][bl] : wedges[rbuf][bl];

            // Publish slot 0: our carry from before this chunk.
            if (wprod) wedges[e & 1][0] = cur.w;
            if (cprod) {
                uint32_t a = ced_remote + (uint32_t)((e & 1) * CHUNK * 4);
                asm volatile("st.shared::cluster.f32 [%0], %1;"
                             :: "r"(a), "f"(cur.w) : "memory");
            }

#pragma unroll
            for (int j = 0; j < CHUNK; ++j) {
                const int t = t0 + j;
                const float4 xv = xq[j];
                if (c + 1 < NCHUNK) xq[j] = xr[(size_t)(t + CHUNK) * RS];

                if (c == 0 && j == 0) {
                    cur = xv;  // init row: out[0] = x[0]
                } else {
                    float up = __shfl_up_sync(0xffffffffu, cur.w, 1);
                    const float bc = __shfl_sync(0xffffffffu, bv, j);
                    if (lane == 0) up = (level == 0) ? NEG_INF : bc;

                    float4 n;
                    n.x = xv.x + fmaxf(cur.x, up);
                    n.y = xv.y + fmaxf(cur.y, cur.x);
                    n.z = xv.z + fmaxf(cur.z, cur.y);
                    n.w = xv.w + fmaxf(cur.w, cur.z);
                    cur = n;
                }

                orow[(size_t)t * RS] = cur;

                if (j < CHUNK - 1) {
                    if (wprod) wedges[e & 1][j + 1] = cur.w;
                    if (cprod) {
                        uint32_t a = ced_remote +
                            (uint32_t)(((e & 1) * CHUNK + j + 1) * 4);
                        asm volatile("st.shared::cluster.f32 [%0], %1;"
                                     :: "r"(a), "f"(cur.w) : "memory");
                    }
                }
            }
        }

        // Cluster-wide barrier: orders local smem + DSMEM edge writes for the
        // next epoch's consumers (arrive has cluster-scope release semantics).
        asm volatile("barrier.cluster.arrive.aligned;" ::: "memory");
        asm volatile("barrier.cluster.wait.aligned;" ::: "memory");
    }
}

extern "C" void kernel_launch(void* const* d_in, const int* in_sizes, int n_in,
                              void* d_out, int out_size) {
    const float* x = (const float*)d_in[0];
    float* out = (float*)d_out;
    const int B = in_sizes[0] / (T * K);
    harddtw_cluster_kernel<<<B * NSPLIT, THREADS>>>(x, out);
}